// round 11
// baseline (speedup 1.0000x reference)
#include <cuda_runtime.h>

// Problem constants
#define BATCH 32
#define H 512
#define W 512
#define HH 256   // half resolution

// Accumulators: [0]=rec, [1]=reg, [2]=wav1, [3]=wav2, [4]=wav3
__device__ double g_acc[5];
// Level-1 Haar LL band scratch: (32, 256, 256) floats = 8 MB
__device__ __align__(16) float g_LL1[(size_t)BATCH * HH * HH];

__device__ __forceinline__ float warp_sum(float v) {
#pragma unroll
    for (int o = 16; o > 0; o >>= 1)
        v += __shfl_xor_sync(0xffffffffu, v, o);
    return v;
}

__global__ void k_zero() {
#pragma unroll
    for (int i = 0; i < 5; i++) g_acc[i] = 0.0;
}

// ---------------------------------------------------------------------------
// K1: fused g1/g2 construction + 3x3 conv + clip + rec/reg MSE partials +
//     level-1 Haar (wav1 partial + LL1 write).
// Block: 16x16 threads, each thread computes a 2x2 block of `out`
//        -> 32x32 output tile per block. Grid (16,16,32).
// ---------------------------------------------------------------------------
__global__ __launch_bounds__(256) void k1(const float* __restrict__ noisy,
                                          const float* __restrict__ wt) {
    const int b  = blockIdx.z;
    const int X0 = blockIdx.x * 32;
    const int Y0 = blockIdx.y * 32;
    const int Ks = (Y0 >> 1) - 1;   // p0/p3 subtile row origin (may be -1)
    const int Ls = (X0 >> 1) - 1;

    __shared__ float p0s[18][19];
    __shared__ float p3s[18][19];
    __shared__ float g1s[34][35];
    __shared__ float red[3][8];

    const int tx  = threadIdx.x, ty = threadIdx.y;
    const int tid = ty * 16 + tx;
    const float* img = noisy + (size_t)b * H * W;

    // Stage checkerboard phases: p0 = noisy[2k][2l], p3 = noisy[2k+1][2l+1]
    for (int i = tid; i < 18 * 18; i += 256) {
        int r = i / 18, c = i % 18;
        int gk = min(max(Ks + r, 0), HH - 1);
        int gl = min(max(Ls + c, 0), HH - 1);
        p0s[r][c] = img[(2 * gk) * W + 2 * gl];
        p3s[r][c] = img[(2 * gk + 1) * W + 2 * gl + 1];
    }
    __syncthreads();

    // Build g1 tile with conv halo: coords [Y0-1, Y0+32] x [X0-1, X0+32].
    // Outside the image -> 0 (conv SAME zero padding). Inside -> clamped
    // half-pixel bilinear upsample of p0 (jax linear resize semantics).
    for (int i = tid; i < 34 * 34; i += 256) {
        int r = i / 34, c = i % 34;
        int gy = Y0 - 1 + r, gx = X0 - 1 + c;
        float v = 0.0f;
        if ((unsigned)gy < H && (unsigned)gx < W) {
            int   iy  = (gy - 1) >> 1;            // floor((gy-1)/2), handles gy=0
            int   ix  = (gx - 1) >> 1;
            float wy1 = (gy & 1) ? 0.25f : 0.75f; // weight of index iy+1
            float wx1 = (gx & 1) ? 0.25f : 0.75f;
            int r0 = max(iy, 0) - Ks, r1 = min(iy + 1, HH - 1) - Ks;
            int c0 = max(ix, 0) - Ls, c1 = min(ix + 1, HH - 1) - Ls;
            float top = p0s[r0][c0] * (1.0f - wx1) + p0s[r0][c1] * wx1;
            float bot = p0s[r1][c0] * (1.0f - wx1) + p0s[r1][c1] * wx1;
            v = top * (1.0f - wy1) + bot * wy1;
        }
        g1s[r][c] = v;
    }
    __syncthreads();

    const float w0 = wt[0], w1 = wt[1], w2 = wt[2],
                w3 = wt[3], w4 = wt[4], w5 = wt[5],
                w6 = wt[6], w7 = wt[7], w8 = wt[8];

    float rec = 0.0f, reg = 0.0f, wav1 = 0.0f;
    float o[2][2];

#pragma unroll
    for (int oy = 0; oy < 2; oy++) {
#pragma unroll
        for (int ox = 0; ox < 2; ox++) {
            int ly = 2 * ty + oy;
            int lx = 2 * tx + ox;
            // 3x3 correlation (zero-padded halo already in g1s)
            float acc = w0 * g1s[ly    ][lx] + w1 * g1s[ly    ][lx + 1] + w2 * g1s[ly    ][lx + 2]
                      + w3 * g1s[ly + 1][lx] + w4 * g1s[ly + 1][lx + 1] + w5 * g1s[ly + 1][lx + 2]
                      + w6 * g1s[ly + 2][lx] + w7 * g1s[ly + 2][lx + 1] + w8 * g1s[ly + 2][lx + 2];
            float outv = fminf(fmaxf(acc, 0.0f), 1.0f);

            int gy = Y0 + ly, gx = X0 + lx;
            // g2 = clamped bilinear upsample of p3 at (gy,gx)
            int   iy  = (gy - 1) >> 1;
            int   ix  = (gx - 1) >> 1;
            float wy1 = (gy & 1) ? 0.25f : 0.75f;
            float wx1 = (gx & 1) ? 0.25f : 0.75f;
            int r0 = max(iy, 0) - Ks, r1 = min(iy + 1, HH - 1) - Ks;
            int c0 = max(ix, 0) - Ls, c1 = min(ix + 1, HH - 1) - Ls;
            float top = p3s[r0][c0] * (1.0f - wx1) + p3s[r0][c1] * wx1;
            float bot = p3s[r1][c0] * (1.0f - wx1) + p3s[r1][c1] * wx1;
            float g2  = top * (1.0f - wy1) + bot * wy1;

            float g1c = g1s[ly + 1][lx + 1];
            float d2 = outv - g2;  rec += d2 * d2;
            float d1 = outv - g1c; reg += d1 * d1;
            o[oy][ox] = outv;
        }
    }

    // Level-1 Haar on the thread's 2x2 output quad
    {
        const float T1 = (50.0f / 255.0f) * 0.25f;  // THRESHOLD / 2^2
        float a = o[0][0], bb = o[0][1], cc = o[1][0], dd = o[1][1];
        float lh = (a - bb + cc - dd) * 0.5f;
        float hl = (a + bb - cc - dd) * 0.5f;
        float hh = (a - bb - cc + dd) * 0.5f;
        wav1 += fminf(fabsf(lh), T1) + fminf(fabsf(hl), T1) + fminf(fabsf(hh), T1);
        float ll = (a + bb + cc + dd) * 0.5f;
        g_LL1[((size_t)b * HH + (Y0 >> 1) + ty) * HH + (X0 >> 1) + tx] = ll;
    }

    // Block reduction -> atomic double accumulation
    rec  = warp_sum(rec);
    reg  = warp_sum(reg);
    wav1 = warp_sum(wav1);
    int lane = tid & 31, wid = tid >> 5;
    if (lane == 0) { red[0][wid] = rec; red[1][wid] = reg; red[2][wid] = wav1; }
    __syncthreads();
    if (tid == 0) {
        double sa = 0.0, sb = 0.0, sc = 0.0;
#pragma unroll
        for (int i = 0; i < 8; i++) { sa += red[0][i]; sb += red[1][i]; sc += red[2][i]; }
        atomicAdd(&g_acc[0], sa);
        atomicAdd(&g_acc[1], sb);
        atomicAdd(&g_acc[2], sc);
    }
}

// ---------------------------------------------------------------------------
// K2: Haar levels 2 and 3 on LL1. Each thread owns a 4x4 LL1 patch:
//     4 level-2 quads -> wav2 + 2x2 LL2 in registers -> 1 level-3 quad -> wav3.
// Block 16x16 threads -> 64x64 LL1 tile. Grid (4,4,32).
// ---------------------------------------------------------------------------
__global__ __launch_bounds__(256) void k2() {
    const int b  = blockIdx.z;
    const int tx = threadIdx.x, ty = threadIdx.y;
    const int tid = ty * 16 + tx;
    const float* base = g_LL1 + (size_t)b * HH * HH;
    const int r0 = blockIdx.y * 64 + 4 * ty;
    const int c0 = blockIdx.x * 64 + 4 * tx;

    float v[4][4];
#pragma unroll
    for (int i = 0; i < 4; i++) {
        float4 q = *reinterpret_cast<const float4*>(base + (size_t)(r0 + i) * HH + c0);
        v[i][0] = q.x; v[i][1] = q.y; v[i][2] = q.z; v[i][3] = q.w;
    }

    const float T2 = (50.0f / 255.0f) * 0.5f;
    const float T3 = (50.0f / 255.0f);
    float wav2 = 0.0f, wav3 = 0.0f;
    float ll2[2][2];

#pragma unroll
    for (int sy = 0; sy < 2; sy++) {
#pragma unroll
        for (int sx = 0; sx < 2; sx++) {
            float a  = v[2 * sy][2 * sx],     bb = v[2 * sy][2 * sx + 1];
            float cc = v[2 * sy + 1][2 * sx], dd = v[2 * sy + 1][2 * sx + 1];
            float lh = (a - bb + cc - dd) * 0.5f;
            float hl = (a + bb - cc - dd) * 0.5f;
            float hh = (a - bb - cc + dd) * 0.5f;
            wav2 += fminf(fabsf(lh), T2) + fminf(fabsf(hl), T2) + fminf(fabsf(hh), T2);
            ll2[sy][sx] = (a + bb + cc + dd) * 0.5f;
        }
    }
    {
        float a = ll2[0][0], bb = ll2[0][1], cc = ll2[1][0], dd = ll2[1][1];
        float lh = (a - bb + cc - dd) * 0.5f;
        float hl = (a + bb - cc - dd) * 0.5f;
        float hh = (a - bb - cc + dd) * 0.5f;
        wav3 += fminf(fabsf(lh), T3) + fminf(fabsf(hl), T3) + fminf(fabsf(hh), T3);
    }

    __shared__ float red[2][8];
    wav2 = warp_sum(wav2);
    wav3 = warp_sum(wav3);
    int lane = tid & 31, wid = tid >> 5;
    if (lane == 0) { red[0][wid] = wav2; red[1][wid] = wav3; }
    __syncthreads();
    if (tid == 0) {
        double s2 = 0.0, s3 = 0.0;
#pragma unroll
        for (int i = 0; i < 8; i++) { s2 += red[0][i]; s3 += red[1][i]; }
        atomicAdd(&g_acc[3], s2);
        atomicAdd(&g_acc[4], s3);
    }
}

// ---------------------------------------------------------------------------
// K3: combine partial sums into final scalar.
// ---------------------------------------------------------------------------
__global__ void k3(float* __restrict__ out) {
    const double N  = (double)BATCH * H * W;            // 8388608
    const double N1 = (double)BATCH * HH * HH;          // 2097152
    const double N2 = N1 * 0.25;                        // 524288
    const double N3 = N2 * 0.25;                        // 131072
    double rec = g_acc[0] / N;
    double reg = g_acc[1] / N;
    double n2n = rec + 2.0 * reg;                       // GAMMA = 2
    double wav = (1.0 / 3.0) * (g_acc[2] / (3.0 * N1))
               + 0.5        * (g_acc[3] / (3.0 * N2))
               + 1.0        * (g_acc[4] / (3.0 * N3));
    out[0] = (float)(n2n + 0.05 * wav);                 // WAVELET_WEIGHT
}

extern "C" void kernel_launch(void* const* d_in, const int* in_sizes, int n_in,
                              void* d_out, int out_size) {
    const float* noisy = (const float*)d_in[0];
    const float* wt    = (const float*)d_in[1];
    float* out         = (float*)d_out;

    k_zero<<<1, 1>>>();
    dim3 blk(16, 16);
    dim3 g1(16, 16, BATCH);   // 32x32 output tiles over 512x512, 32 images
    k1<<<g1, blk>>>(noisy, wt);
    dim3 g2(4, 4, BATCH);     // 64x64 LL1 tiles over 256x256
    k2<<<g2, blk>>>();
    k3<<<1, 1>>>(out);
}